// round 9
// baseline (speedup 1.0000x reference)
#include <cuda_runtime.h>
#include <cuda_bf16.h>
#include <math.h>
#include <float.h>

#define An    8
#define Bn    4096
#define FEATn 2560
#define SQRTD 11.3137085f

typedef unsigned long long u64;

// ------------- static device scratch (no allocation) -------------
__device__ float g_M1[256 * 128];        // [e][h*64+o]
__device__ float g_M2[256 * 64];         // [e][h*32+p]
__device__ float g_logit1[16 * Bn * 7];  // [pair=h*8+a][b][n]
__device__ float g_denom1[16];
__device__ float g_lp[16 * Bn * 64];     // [pair][b][c]
__device__ float g_denom2[16];
__device__ float g_pmax[16 * 32 * 64];
__device__ int   g_pargb[16 * 32 * 64];

// ---- packed fp32x2 helpers (sm_103a FFMA2) ----
__device__ __forceinline__ void ffma2(u64& acc, u64 x, u64 w) {
    asm("fma.rn.f32x2 %0, %1, %2, %0;" : "+l"(acc) : "l"(x), "l"(w));
}
__device__ __forceinline__ u64 pack2(float lo, float hi) {
    u64 r; asm("mov.b64 %0, {%1, %2};" : "=l"(r) : "f"(lo), "f"(hi)); return r;
}
__device__ __forceinline__ float2 unpack2(u64 v) {
    float2 f; asm("mov.b64 {%0, %1}, %2;" : "=f"(f.x), "=f"(f.y) : "l"(v)); return f;
}

// ---------------- K0: fused selection/key weights ----------------
__global__ void k0_prep(const float* __restrict__ Wsel_nb, const float* __restrict__ Wk_nb,
                        const float* __restrict__ Wsel_poi, const float* __restrict__ Wk_poi) {
    int idx = blockIdx.x * 256 + threadIdx.x;
    if (idx < 32768) {
        int e = idx >> 7, ho = idx & 127;
        int h = ho >> 6, o = ho & 63;
        const float* ws = Wsel_nb + h * 32768;  // [d][e] stride 256
        const float* wk = Wk_nb + h * 8192;     // [d][o] stride 64
        float s = 0.f;
        for (int d = 0; d < 128; d++) s += ws[d * 256 + e] * wk[d * 64 + o];
        g_M1[e * 128 + ho] = s;
    } else if (idx < 49152) {
        int i2 = idx - 32768;
        int e = i2 >> 6, hp = i2 & 63;
        int h = hp >> 5, p = hp & 31;
        const float* ws = Wsel_poi + h * 32768;
        const float* wk = Wk_poi + h * 4096;    // [d][p] stride 32
        float s = 0.f;
        for (int d = 0; d < 128; d++) s += ws[d * 256 + e] * wk[d * 32 + p];
        g_M2[e * 64 + hp] = s;
    }
}

// ---------------- K1: enc -> u -> stage-1 logits ----------------
// grid (256, 8): 16 b-rows per block. 256 threads. Weights in registers.
__global__ __launch_bounds__(256, 2)
void k1_stage1(const float* __restrict__ obs, const float* __restrict__ Wenc,
               const float* __restrict__ benc) {
    __shared__ __align__(16) float Fself[16 * 64];
    __shared__ __align__(16) float Fenc[16 * 256];
    __shared__ __align__(16) float Fu[16 * 128];
    const int a = blockIdx.y, b0 = blockIdx.x * 16, tid = threadIdx.x;

    // per-thread weight row (col = tid): 64 floats as 16 packed ulonglong2
    ulonglong2 wreg[16];
    {
        const ulonglong2* gw = (const ulonglong2*)(Wenc + (size_t)tid * 64);
#pragma unroll
        for (int i = 0; i < 16; i++) wreg[i] = gw[i];
    }
    float bb = benc[tid];

    // self tile: 16 rows x 64
    {
        int r = tid >> 4, q = (tid & 15) * 4;
        *(float4*)(Fself + r * 64 + q) =
            *(const float4*)(obs + ((size_t)a * Bn + b0 + r) * FEATn + 448 + q);
    }
    __syncthreads();

    // enc = leaky(self @ Wenc^T + b), FFMA2 packed over k
    {
        u64 acc2[16];
#pragma unroll
        for (int r = 0; r < 16; r++) acc2[r] = 0ull;
#pragma unroll
        for (int kc = 0; kc < 16; kc++) {
            ulonglong2 w2 = wreg[kc];
#pragma unroll
            for (int r = 0; r < 16; r++) {
                ulonglong2 x2 = *(const ulonglong2*)(&Fself[r * 64 + kc * 4]);
                ffma2(acc2[r], x2.x, w2.x);
                ffma2(acc2[r], x2.y, w2.y);
            }
        }
#pragma unroll
        for (int r = 0; r < 16; r++) {
            float2 f = unpack2(acc2[r]);
            float v = f.x + f.y + bb;
            Fenc[r * 256 + tid] = (v >= 0.f) ? v : 0.01f * v;
        }
    }
    __syncthreads();

    // u = enc @ M1 : 16 rows x 128 cols, K=256 (M1 from global, L1-resident)
    {
        int col = tid & 127, rh = tid >> 7;
        u64 uacc[8];
#pragma unroll
        for (int i = 0; i < 8; i++) uacc[i] = 0ull;
#pragma unroll 2
        for (int kc = 0; kc < 64; kc++) {
            int k = kc * 4;
            float m0 = g_M1[(k + 0) * 128 + col];
            float m1 = g_M1[(k + 1) * 128 + col];
            float m2 = g_M1[(k + 2) * 128 + col];
            float m3 = g_M1[(k + 3) * 128 + col];
            u64 mA = pack2(m0, m1), mB = pack2(m2, m3);
#pragma unroll
            for (int i = 0; i < 8; i++) {
                ulonglong2 e2 = *(const ulonglong2*)(&Fenc[(rh * 8 + i) * 256 + k]);
                ffma2(uacc[i], e2.x, mA);
                ffma2(uacc[i], e2.y, mB);
            }
        }
#pragma unroll
        for (int i = 0; i < 8; i++) {
            float2 f = unpack2(uacc[i]);
            Fu[(rh * 8 + i) * 128 + col] = f.x + f.y;
        }
    }
    __syncthreads();

    // logits1: warp per 2 rows
    {
        int w = tid >> 5, lane = tid & 31;
        for (int rr = 0; rr < 2; rr++) {
            int r = w * 2 + rr, b = b0 + r;
            float u0 = Fu[r * 128 + lane], u1 = Fu[r * 128 + 32 + lane];
            float u2 = Fu[r * 128 + 64 + lane], u3 = Fu[r * 128 + 96 + lane];
            const float* x = obs + ((size_t)a * Bn + b) * FEATn;
#pragma unroll
            for (int n = 0; n < 7; n++) {
                float xa = x[n * 64 + lane], xb = x[n * 64 + 32 + lane];
                float p0 = xa * u0 + xb * u1;   // h=0
                float p1 = xa * u2 + xb * u3;   // h=1
#pragma unroll
                for (int off = 16; off; off >>= 1) {
                    p0 += __shfl_xor_sync(0xffffffffu, p0, off);
                    p1 += __shfl_xor_sync(0xffffffffu, p1, off);
                }
                if (lane == 0) {
                    g_logit1[((size_t)a * Bn + b) * 7 + n] = p0 / SQRTD;
                    g_logit1[((size_t)(8 + a) * Bn + b) * 7 + n] = p1 / SQRTD;
                }
            }
        }
    }
}

// ---------------- K2: deterministic mean over (B,7) per pair (bit-identical) ---
__global__ void k2_mean1() {
    int pair = blockIdx.x;
    const float* p = g_logit1 + (size_t)pair * Bn * 7;
    float s = 0.f;
    for (int i = threadIdx.x; i < Bn * 7; i += 256) s += p[i];
    __shared__ float red[256];
    red[threadIdx.x] = s;
    __syncthreads();
    for (int st = 128; st; st >>= 1) {
        if (threadIdx.x < st) red[threadIdx.x] += red[threadIdx.x + st];
        __syncthreads();
    }
    if (threadIdx.x == 0) g_denom1[pair] = red[0] / 28672.0f + 1e-9f;
}

// ---------------- K3: w-softmax, V-weighted sum, t, lp ----------------
// grid (256, 8): 16 b-rows per block, weights in registers, FFMA2.
__global__ __launch_bounds__(256, 2)
void k3_stage2(const float* __restrict__ obs, const float* __restrict__ Wv,
               const float* __restrict__ bv) {
    __shared__ __align__(16) float Fx[16 * 64];
    __shared__ __align__(16) float Fw[16 * 16];
    __shared__ __align__(16) float Fnb[16 * 256];
    __shared__ __align__(16) float Ft[16 * 64];
    const int a = blockIdx.y, b0 = blockIdx.x * 16, tid = threadIdx.x;
    const int h = tid >> 7;

    ulonglong2 wreg[16];
    {
        const ulonglong2* gw = (const ulonglong2*)(Wv + (size_t)tid * 64);
#pragma unroll
        for (int i = 0; i < 16; i++) wreg[i] = gw[i];
    }
    float bb = bv[tid];

    if (tid < 32) {  // stage-1 softmax weights per (row, h) — serial, bit-stable
        int r = tid >> 1, h2 = tid & 1, pair = h2 * 8 + a, b = b0 + r;
        const float* lg = g_logit1 + ((size_t)pair * Bn + b) * 7;
        float dn = g_denom1[pair];
        float L[7], m = -FLT_MAX, s = 0.f;
#pragma unroll
        for (int n = 0; n < 7; n++) { L[n] = lg[n] / dn; m = fmaxf(m, L[n]); }
#pragma unroll
        for (int n = 0; n < 7; n++) { L[n] = expf(L[n] - m); s += L[n]; }
#pragma unroll
        for (int n = 0; n < 7; n++) Fw[r * 16 + h2 * 8 + n] = L[n] / s;
    }

    float nbacc[16];
#pragma unroll
    for (int r = 0; r < 16; r++) nbacc[r] = 0.f;

    for (int n = 0; n < 7; n++) {
        __syncthreads();
        {
            int r = tid >> 4, q = (tid & 15) * 4;
            *(float4*)(Fx + r * 64 + q) =
                *(const float4*)(obs + ((size_t)a * Bn + b0 + r) * FEATn + n * 64 + q);
        }
        __syncthreads();
#pragma unroll
        for (int chunk = 0; chunk < 2; chunk++) {
            u64 acc2[8];
#pragma unroll
            for (int r = 0; r < 8; r++) acc2[r] = 0ull;
#pragma unroll
            for (int kc = 0; kc < 16; kc++) {
                ulonglong2 w2 = wreg[kc];
#pragma unroll
                for (int r = 0; r < 8; r++) {
                    ulonglong2 x2 = *(const ulonglong2*)(&Fx[(chunk * 8 + r) * 64 + kc * 4]);
                    ffma2(acc2[r], x2.x, w2.x);
                    ffma2(acc2[r], x2.y, w2.y);
                }
            }
#pragma unroll
            for (int r = 0; r < 8; r++) {
                float2 f = unpack2(acc2[r]);
                float v = f.x + f.y + bb;
                v = (v >= 0.f) ? v : 0.01f * v;
                nbacc[chunk * 8 + r] += Fw[(chunk * 8 + r) * 16 + h * 8 + n] * v;
            }
        }
    }
    __syncthreads();
#pragma unroll
    for (int r = 0; r < 16; r++) Fnb[r * 256 + tid] = nbacc[r];
    __syncthreads();

    // t[r][hp] = (nb_all[r] . M2[:,hp]) / sqrt(D), FFMA2 packed over e
    {
        int hp = tid & 63, g = tid >> 6;
        u64 tacc[4];
#pragma unroll
        for (int i = 0; i < 4; i++) tacc[i] = 0ull;
#pragma unroll 2
        for (int ec = 0; ec < 64; ec++) {
            int e = ec * 4;
            float m0 = g_M2[(e + 0) * 64 + hp];
            float m1 = g_M2[(e + 1) * 64 + hp];
            float m2 = g_M2[(e + 2) * 64 + hp];
            float m3 = g_M2[(e + 3) * 64 + hp];
            u64 mA = pack2(m0, m1), mB = pack2(m2, m3);
#pragma unroll
            for (int i = 0; i < 4; i++) {
                ulonglong2 f2 = *(const ulonglong2*)(&Fnb[(g * 4 + i) * 256 + e]);
                ffma2(tacc[i], f2.x, mA);
                ffma2(tacc[i], f2.y, mB);
            }
        }
#pragma unroll
        for (int i = 0; i < 4; i++) {
            float2 f = unpack2(tacc[i]);
            Ft[(g * 4 + i) * 64 + hp] = (f.x + f.y) * (1.0f / SQRTD);
        }
    }
    __syncthreads();

    // lp[h][c] = dot(t[h], cargo0[b][c]) ; warp per 2 rows
    {
        int w = tid >> 5, lane = tid & 31;
        for (int rr = 0; rr < 2; rr++) {
            int r = w * 2 + rr, b = b0 + r;
            float t0 = Ft[r * 64 + lane], t1 = Ft[r * 64 + 32 + lane];
            const float* cg = obs + (size_t)b * FEATn + 512;  // agent 0 cargo
            float* o0 = g_lp + ((size_t)a * Bn + b) * 64;
            float* o1 = g_lp + ((size_t)(8 + a) * Bn + b) * 64;
            for (int c = 0; c < 64; c++) {
                float x = cg[c * 32 + lane];
                float p0 = t0 * x, p1 = t1 * x;
#pragma unroll
                for (int off = 16; off; off >>= 1) {
                    p0 += __shfl_xor_sync(0xffffffffu, p0, off);
                    p1 += __shfl_xor_sync(0xffffffffu, p1, off);
                }
                if (lane == 0) { o0[c] = p0; o1[c] = p1; }
            }
        }
    }
}

// ---------------- K4: deterministic mean over (B,64) per pair (bit-identical) --
__global__ void k4_mean2() {
    int pair = blockIdx.x;
    const float* p = g_lp + (size_t)pair * Bn * 64;
    float s = 0.f;
    for (int i = threadIdx.x; i < Bn * 64; i += 256) s += p[i];
    __shared__ float red[256];
    red[threadIdx.x] = s;
    __syncthreads();
    for (int st = 128; st; st >>= 1) {
        if (threadIdx.x < st) red[threadIdx.x] += red[threadIdx.x + st];
        __syncthreads();
    }
    if (threadIdx.x == 0) g_denom2[pair] = red[0] / 262144.0f + 1e-9f;
}

// ---------------- K5: fused softmax + column (max, first-b) stats --------------
// grid (16 pairs, 32 chunks of 128 b). warp per 16 rows. No wp writeback.
__global__ void k5_stats() {
    int pair = blockIdx.x, chunk = blockIdx.y;
    int w = threadIdx.x >> 5, lane = threadIdx.x & 31;
    float d = g_denom2[pair];
    float m0 = -FLT_MAX, m1 = -FLT_MAX;
    int a0 = 1 << 30, a1 = 1 << 30;
    int brow0 = chunk * 128 + w * 16;
    for (int i = 0; i < 16; i++) {
        int b = brow0 + i;
        const float* p = g_lp + ((size_t)pair * Bn + b) * 64;
        float L0 = p[lane] / d, L1 = p[lane + 32] / d;
        float mx = fmaxf(L0, L1);
#pragma unroll
        for (int off = 16; off; off >>= 1) mx = fmaxf(mx, __shfl_xor_sync(0xffffffffu, mx, off));
        float e0 = expf(L0 - mx), e1 = expf(L1 - mx);
        float s = e0 + e1;
#pragma unroll
        for (int off = 16; off; off >>= 1) s += __shfl_xor_sync(0xffffffffu, s, off);
        float inv = 1.0f / s;
        float w0 = e0 * inv, w1 = e1 * inv;
        if (w0 > m0) { m0 = w0; a0 = b; }  // ascending b: strict > keeps first
        if (w1 > m1) { m1 = w1; a1 = b; }
    }
    __shared__ float sv[8 * 64];
    __shared__ int sb[8 * 64];
    sv[w * 64 + lane] = m0;        sb[w * 64 + lane] = a0;
    sv[w * 64 + lane + 32] = m1;   sb[w * 64 + lane + 32] = a1;
    __syncthreads();
    if (threadIdx.x < 64) {
        int c = threadIdx.x;
        float bvv = sv[c];
        int bbb = sb[c];
        for (int j = 1; j < 8; j++) {  // ascending warp = ascending b
            float v2 = sv[j * 64 + c];
            int b2 = sb[j * 64 + c];
            if (v2 > bvv || (v2 == bvv && b2 < bbb)) { bvv = v2; bbb = b2; }
        }
        g_pmax[(pair * 32 + chunk) * 64 + c] = bvv;
        g_pargb[(pair * 32 + chunk) * 64 + c] = bbb;
    }
}

// ---------------- K6: merge stats, 16-step scan, broadcast output --------------
__global__ void k6_scan(const float* __restrict__ obs, float* __restrict__ out) {
    __shared__ float smax[1024];
    __shared__ int sab[1024];
    __shared__ int smask[64];
    __shared__ float sci[8];
    int tid = threadIdx.x;
    for (int i = tid; i < 1024; i += 256) {
        int pair = i >> 6, c = i & 63;
        float bvv = -FLT_MAX;
        int bbb = 1 << 30;
        for (int j = 0; j < 32; j++) {
            float v = g_pmax[(pair * 32 + j) * 64 + c];
            int b2 = g_pargb[(pair * 32 + j) * 64 + c];
            if (v > bvv || (v == bvv && b2 < bbb)) { bvv = v; bbb = b2; }
        }
        smax[i] = bvv;
        sab[i] = bbb;
    }
    if (tid < 64) {
        int off = (32 * tid + 2047) & 2047;           // (32c - 1) mod 2048
        smask[tid] = (obs[512 + off] == 1.0f) ? 1 : 0;  // obs[0,0,512+off]
    }
    __syncthreads();
    if (tid == 0) {
        for (int i = 0; i < 16; i++) {  // i = h*8 + a
            float bestv = -FLT_MAX;
            int bestflat = -1;
            for (int c = 0; c < 64; c++) {
                if (smask[c]) continue;
                float v = smax[i * 64 + c];
                int flat = sab[i * 64 + c] * 64 + c;
                if (bestflat < 0 || v > bestv || (v == bestv && flat < bestflat)) {
                    bestv = v;
                    bestflat = flat;
                }
            }
            int ci = (bestflat < 0) ? 0 : bestflat;
            if (ci < 64) smask[ci] = 1;          // OOB scatter dropped otherwise
            if (i >= 8) sci[i - 8] = (float)ci;  // h=1 pass is the last write
        }
    }
    __syncthreads();
    for (int i = tid; i < 32768; i += 256) out[i] = sci[i >> 12];
}

extern "C" void kernel_launch(void* const* d_in, const int* in_sizes, int n_in,
                              void* d_out, int out_size) {
    const float* obs = (const float*)d_in[0];
    const float* Wenc = (const float*)d_in[1];
    const float* benc = (const float*)d_in[2];
    const float* Wk_nb = (const float*)d_in[3];
    const float* Wsel_nb = (const float*)d_in[4];
    const float* Wv_nb = (const float*)d_in[5];
    const float* bv_nb = (const float*)d_in[6];
    const float* Wk_poi = (const float*)d_in[7];
    const float* Wsel_poi = (const float*)d_in[8];
    // d_in[9] = Wv_poi, d_in[10] = bv_poi : unused by the reference
    float* out = (float*)d_out;

    k0_prep<<<192, 256>>>(Wsel_nb, Wk_nb, Wsel_poi, Wk_poi);
    k1_stage1<<<dim3(256, 8), 256>>>(obs, Wenc, benc);
    k2_mean1<<<16, 256>>>();
    k3_stage2<<<dim3(256, 8), 256>>>(obs, Wv_nb, bv_nb);
    k4_mean2<<<16, 256>>>();
    k5_stats<<<dim3(16, 32), 256>>>();
    k6_scan<<<1, 256>>>(obs, out);
}

// round 10
// speedup vs baseline: 1.1582x; 1.1582x over previous
#include <cuda_runtime.h>
#include <cuda_bf16.h>
#include <math.h>
#include <float.h>

#define An    8
#define Bn    4096
#define FEATn 2560
#define SQRTD 11.3137085f

typedef unsigned long long u64;

// ------------- static device scratch (no allocation) -------------
__device__ float g_M1[256 * 128];        // [e][h*64+o]
__device__ float g_M2[256 * 64];         // [e][h*32+p]
__device__ float g_logit1[16 * Bn * 7];  // [pair=h*8+a][b][n]
__device__ float g_denom1[16];
__device__ float g_lp[16 * Bn * 64];     // [pair][b][c]
__device__ float g_denom2[16];
__device__ float g_pmax[16 * 32 * 64];
__device__ int   g_pargb[16 * 32 * 64];
__device__ float g_cargoT[(size_t)Bn * 2048];  // [b][p*64+c]

// ---- packed fp32x2 helpers (sm_103a FFMA2) ----
__device__ __forceinline__ void ffma2(u64& acc, u64 x, u64 w) {
    asm("fma.rn.f32x2 %0, %1, %2, %0;" : "+l"(acc) : "l"(x), "l"(w));
}
__device__ __forceinline__ u64 pack2(float lo, float hi) {
    u64 r; asm("mov.b64 %0, {%1, %2};" : "=l"(r) : "f"(lo), "f"(hi)); return r;
}
__device__ __forceinline__ float2 unpack2(u64 v) {
    float2 f; asm("mov.b64 {%0, %1}, %2;" : "=f"(f.x), "=f"(f.y) : "l"(v)); return f;
}

// ---------------- K0: fused selection/key weights ----------------
__global__ void k0_prep(const float* __restrict__ Wsel_nb, const float* __restrict__ Wk_nb,
                        const float* __restrict__ Wsel_poi, const float* __restrict__ Wk_poi) {
    int idx = blockIdx.x * 256 + threadIdx.x;
    if (idx < 32768) {
        int e = idx >> 7, ho = idx & 127;
        int h = ho >> 6, o = ho & 63;
        const float* ws = Wsel_nb + h * 32768;  // [d][e] stride 256
        const float* wk = Wk_nb + h * 8192;     // [d][o] stride 64
        float s = 0.f;
        for (int d = 0; d < 128; d++) s += ws[d * 256 + e] * wk[d * 64 + o];
        g_M1[e * 128 + ho] = s;
    } else if (idx < 49152) {
        int i2 = idx - 32768;
        int e = i2 >> 6, hp = i2 & 63;
        int h = hp >> 5, p = hp & 31;
        const float* ws = Wsel_poi + h * 32768;
        const float* wk = Wk_poi + h * 4096;    // [d][p] stride 32
        float s = 0.f;
        for (int d = 0; d < 128; d++) s += ws[d * 256 + e] * wk[d * 32 + p];
        g_M2[e * 64 + hp] = s;
    }
}

// ---------------- K_ct: transpose agent-0 cargo [b][c*32+p] -> [b][p*64+c] ----
__global__ void k_ct(const float* __restrict__ obs) {
    __shared__ float T[32 * 65];
    int b = blockIdx.x, tid = threadIdx.x;
    const float4* in = (const float4*)(obs + (size_t)b * FEATn + 512);
    for (int i = tid; i < 512; i += 256) {
        float4 v = in[i];
        int c = i >> 3, p0 = (i & 7) * 4;
        T[(p0 + 0) * 65 + c] = v.x;
        T[(p0 + 1) * 65 + c] = v.y;
        T[(p0 + 2) * 65 + c] = v.z;
        T[(p0 + 3) * 65 + c] = v.w;
    }
    __syncthreads();
    float* ob = g_cargoT + (size_t)b * 2048;
    for (int i = tid; i < 2048; i += 256) ob[i] = T[(i >> 6) * 65 + (i & 63)];
}

// ---------------- K1: enc -> u -> stage-1 logits ----------------
__global__ __launch_bounds__(256, 2)
void k1_stage1(const float* __restrict__ obs, const float* __restrict__ Wenc,
               const float* __restrict__ benc) {
    __shared__ __align__(16) float Fself[16 * 64];
    __shared__ __align__(16) float Fenc[16 * 256];
    __shared__ __align__(16) float Fu[16 * 128];
    const int a = blockIdx.y, b0 = blockIdx.x * 16, tid = threadIdx.x;

    ulonglong2 wreg[16];
    {
        const ulonglong2* gw = (const ulonglong2*)(Wenc + (size_t)tid * 64);
#pragma unroll
        for (int i = 0; i < 16; i++) wreg[i] = gw[i];
    }
    float bb = benc[tid];
    {
        int r = tid >> 4, q = (tid & 15) * 4;
        *(float4*)(Fself + r * 64 + q) =
            *(const float4*)(obs + ((size_t)a * Bn + b0 + r) * FEATn + 448 + q);
    }
    __syncthreads();

    // enc = leaky(self @ Wenc^T + b)
    {
        u64 acc2[16];
#pragma unroll
        for (int r = 0; r < 16; r++) acc2[r] = 0ull;
#pragma unroll
        for (int kc = 0; kc < 16; kc++) {
            ulonglong2 w2 = wreg[kc];
#pragma unroll
            for (int r = 0; r < 16; r++) {
                ulonglong2 x2 = *(const ulonglong2*)(&Fself[r * 64 + kc * 4]);
                ffma2(acc2[r], x2.x, w2.x);
                ffma2(acc2[r], x2.y, w2.y);
            }
        }
#pragma unroll
        for (int r = 0; r < 16; r++) {
            float2 f = unpack2(acc2[r]);
            float v = f.x + f.y + bb;
            Fenc[r * 256 + tid] = (v >= 0.f) ? v : 0.01f * v;
        }
    }
    __syncthreads();

    // u = enc @ M1 : 16x128, K=256
    {
        int col = tid & 127, rh = tid >> 7;
        u64 uacc[8];
#pragma unroll
        for (int i = 0; i < 8; i++) uacc[i] = 0ull;
#pragma unroll 2
        for (int kc = 0; kc < 64; kc++) {
            int k = kc * 4;
            u64 mA = pack2(g_M1[(k + 0) * 128 + col], g_M1[(k + 1) * 128 + col]);
            u64 mB = pack2(g_M1[(k + 2) * 128 + col], g_M1[(k + 3) * 128 + col]);
#pragma unroll
            for (int i = 0; i < 8; i++) {
                ulonglong2 e2 = *(const ulonglong2*)(&Fenc[(rh * 8 + i) * 256 + k]);
                ffma2(uacc[i], e2.x, mA);
                ffma2(uacc[i], e2.y, mB);
            }
        }
#pragma unroll
        for (int i = 0; i < 8; i++) {
            float2 f = unpack2(uacc[i]);
            Fu[(rh * 8 + i) * 128 + col] = f.x + f.y;
        }
    }
    __syncthreads();

    // logits1: warp per 2 rows
    {
        int w = tid >> 5, lane = tid & 31;
        for (int rr = 0; rr < 2; rr++) {
            int r = w * 2 + rr, b = b0 + r;
            float u0 = Fu[r * 128 + lane], u1 = Fu[r * 128 + 32 + lane];
            float u2 = Fu[r * 128 + 64 + lane], u3 = Fu[r * 128 + 96 + lane];
            const float* x = obs + ((size_t)a * Bn + b) * FEATn;
#pragma unroll
            for (int n = 0; n < 7; n++) {
                float xa = x[n * 64 + lane], xb = x[n * 64 + 32 + lane];
                float p0 = xa * u0 + xb * u1;
                float p1 = xa * u2 + xb * u3;
#pragma unroll
                for (int off = 16; off; off >>= 1) {
                    p0 += __shfl_xor_sync(0xffffffffu, p0, off);
                    p1 += __shfl_xor_sync(0xffffffffu, p1, off);
                }
                if (lane == 0) {
                    g_logit1[((size_t)a * Bn + b) * 7 + n] = p0 / SQRTD;
                    g_logit1[((size_t)(8 + a) * Bn + b) * 7 + n] = p1 / SQRTD;
                }
            }
        }
    }
}

// ---------------- K2: deterministic mean over (B,7) per pair ----------------
__global__ void k2_mean1() {
    int pair = blockIdx.x;
    const float* p = g_logit1 + (size_t)pair * Bn * 7;
    float s = 0.f;
    for (int i = threadIdx.x; i < Bn * 7; i += 256) s += p[i];
    __shared__ float red[256];
    red[threadIdx.x] = s;
    __syncthreads();
    for (int st = 128; st; st >>= 1) {
        if (threadIdx.x < st) red[threadIdx.x] += red[threadIdx.x + st];
        __syncthreads();
    }
    if (threadIdx.x == 0) g_denom1[pair] = red[0] / 28672.0f + 1e-9f;
}

// ---------------- K3: w-softmax, V-weighted sum, t, lp ----------------
__global__ __launch_bounds__(256, 2)
void k3_stage2(const float* __restrict__ obs, const float* __restrict__ Wv,
               const float* __restrict__ bv) {
    __shared__ __align__(16) float Fx[16 * 64];
    __shared__ __align__(16) float Fw[16 * 16];
    __shared__ __align__(16) float Fnb[16 * 256];
    __shared__ __align__(16) float Ft[16 * 64];
    const int a = blockIdx.y, b0 = blockIdx.x * 16, tid = threadIdx.x;
    const int h = tid >> 7;

    ulonglong2 wreg[16];
    {
        const ulonglong2* gw = (const ulonglong2*)(Wv + (size_t)tid * 64);
#pragma unroll
        for (int i = 0; i < 16; i++) wreg[i] = gw[i];
    }
    float bb = bv[tid];

    if (tid < 32) {  // stage-1 softmax weights per (row, h)
        int r = tid >> 1, h2 = tid & 1, pair = h2 * 8 + a, b = b0 + r;
        const float* lg = g_logit1 + ((size_t)pair * Bn + b) * 7;
        float dn = g_denom1[pair];
        float L[7], m = -FLT_MAX, s = 0.f;
#pragma unroll
        for (int n = 0; n < 7; n++) { L[n] = lg[n] / dn; m = fmaxf(m, L[n]); }
#pragma unroll
        for (int n = 0; n < 7; n++) { L[n] = expf(L[n] - m); s += L[n]; }
#pragma unroll
        for (int n = 0; n < 7; n++) Fw[r * 16 + h2 * 8 + n] = L[n] / s;
    }

    float nbacc[16];
#pragma unroll
    for (int r = 0; r < 16; r++) nbacc[r] = 0.f;

    for (int n = 0; n < 7; n++) {
        __syncthreads();
        {
            int r = tid >> 4, q = (tid & 15) * 4;
            *(float4*)(Fx + r * 64 + q) =
                *(const float4*)(obs + ((size_t)a * Bn + b0 + r) * FEATn + n * 64 + q);
        }
        __syncthreads();
#pragma unroll
        for (int chunk = 0; chunk < 2; chunk++) {
            u64 acc2[8];
#pragma unroll
            for (int r = 0; r < 8; r++) acc2[r] = 0ull;
#pragma unroll
            for (int kc = 0; kc < 16; kc++) {
                ulonglong2 w2 = wreg[kc];
#pragma unroll
                for (int r = 0; r < 8; r++) {
                    ulonglong2 x2 = *(const ulonglong2*)(&Fx[(chunk * 8 + r) * 64 + kc * 4]);
                    ffma2(acc2[r], x2.x, w2.x);
                    ffma2(acc2[r], x2.y, w2.y);
                }
            }
#pragma unroll
            for (int r = 0; r < 8; r++) {
                float2 f = unpack2(acc2[r]);
                float v = f.x + f.y + bb;
                v = (v >= 0.f) ? v : 0.01f * v;
                nbacc[chunk * 8 + r] += Fw[(chunk * 8 + r) * 16 + h * 8 + n] * v;
            }
        }
    }
    __syncthreads();
#pragma unroll
    for (int r = 0; r < 16; r++) Fnb[r * 256 + tid] = nbacc[r];
    __syncthreads();

    // t[r][hp] = (nb_all[r] . M2[:,hp]) / sqrt(D)
    {
        int hp = tid & 63, g = tid >> 6;
        u64 tacc[4];
#pragma unroll
        for (int i = 0; i < 4; i++) tacc[i] = 0ull;
#pragma unroll 2
        for (int ec = 0; ec < 64; ec++) {
            int e = ec * 4;
            u64 mA = pack2(g_M2[(e + 0) * 64 + hp], g_M2[(e + 1) * 64 + hp]);
            u64 mB = pack2(g_M2[(e + 2) * 64 + hp], g_M2[(e + 3) * 64 + hp]);
#pragma unroll
            for (int i = 0; i < 4; i++) {
                ulonglong2 f2 = *(const ulonglong2*)(&Fnb[(g * 4 + i) * 256 + e]);
                ffma2(tacc[i], f2.x, mA);
                ffma2(tacc[i], f2.y, mB);
            }
        }
#pragma unroll
        for (int i = 0; i < 4; i++) {
            float2 f = unpack2(tacc[i]);
            Ft[(g * 4 + i) * 64 + hp] = (f.x + f.y) * (1.0f / SQRTD);
        }
    }
    __syncthreads();

    // lp: lane = c (coalesced via g_cargoT), no shuffles
    {
        int w = tid >> 5, lane = tid & 31;
        for (int rr = 0; rr < 2; rr++) {
            int r = w * 2 + rr, b = b0 + r;
            const float* ct = g_cargoT + (size_t)b * 2048;
#pragma unroll
            for (int ch = 0; ch < 2; ch++) {
                float acc0 = 0.f, acc1 = 0.f;
#pragma unroll
                for (int p = 0; p < 32; p++) {
                    float x = ct[p * 64 + ch * 32 + lane];
                    acc0 = fmaf(Ft[r * 64 + p], x, acc0);
                    acc1 = fmaf(Ft[r * 64 + 32 + p], x, acc1);
                }
                g_lp[((size_t)a * Bn + b) * 64 + ch * 32 + lane] = acc0;
                g_lp[((size_t)(8 + a) * Bn + b) * 64 + ch * 32 + lane] = acc1;
            }
        }
    }
}

// ---------------- K4: deterministic mean over (B,64) per pair ----------------
__global__ void k4_mean2() {
    int pair = blockIdx.x;
    const float* p = g_lp + (size_t)pair * Bn * 64;
    float s = 0.f;
    for (int i = threadIdx.x; i < Bn * 64; i += 256) s += p[i];
    __shared__ float red[256];
    red[threadIdx.x] = s;
    __syncthreads();
    for (int st = 128; st; st >>= 1) {
        if (threadIdx.x < st) red[threadIdx.x] += red[threadIdx.x + st];
        __syncthreads();
    }
    if (threadIdx.x == 0) g_denom2[pair] = red[0] / 262144.0f + 1e-9f;
}

// ---------------- K5: fused softmax + column (max, first-b) stats ------------
__global__ void k5_stats() {
    int pair = blockIdx.x, chunk = blockIdx.y;
    int w = threadIdx.x >> 5, lane = threadIdx.x & 31;
    float d = g_denom2[pair];
    float m0 = -FLT_MAX, m1 = -FLT_MAX;
    int a0 = 1 << 30, a1 = 1 << 30;
    int brow0 = chunk * 128 + w * 16;
    for (int i = 0; i < 16; i++) {
        int b = brow0 + i;
        const float* p = g_lp + ((size_t)pair * Bn + b) * 64;
        float L0 = p[lane] / d, L1 = p[lane + 32] / d;
        float mx = fmaxf(L0, L1);
#pragma unroll
        for (int off = 16; off; off >>= 1) mx = fmaxf(mx, __shfl_xor_sync(0xffffffffu, mx, off));
        float e0 = expf(L0 - mx), e1 = expf(L1 - mx);
        float s = e0 + e1;
#pragma unroll
        for (int off = 16; off; off >>= 1) s += __shfl_xor_sync(0xffffffffu, s, off);
        float inv = 1.0f / s;
        float w0 = e0 * inv, w1 = e1 * inv;
        if (w0 > m0) { m0 = w0; a0 = b; }
        if (w1 > m1) { m1 = w1; a1 = b; }
    }
    __shared__ float sv[8 * 64];
    __shared__ int sb[8 * 64];
    sv[w * 64 + lane] = m0;        sb[w * 64 + lane] = a0;
    sv[w * 64 + lane + 32] = m1;   sb[w * 64 + lane + 32] = a1;
    __syncthreads();
    if (threadIdx.x < 64) {
        int c = threadIdx.x;
        float bvv = sv[c];
        int bbb = sb[c];
        for (int j = 1; j < 8; j++) {
            float v2 = sv[j * 64 + c];
            int b2 = sb[j * 64 + c];
            if (v2 > bvv || (v2 == bvv && b2 < bbb)) { bvv = v2; bbb = b2; }
        }
        g_pmax[(pair * 32 + chunk) * 64 + c] = bvv;
        g_pargb[(pair * 32 + chunk) * 64 + c] = bbb;
    }
}

// ---------------- K6: merge stats, 16-step scan, broadcast output ------------
__global__ void k6_scan(const float* __restrict__ obs, float* __restrict__ out) {
    __shared__ float smax[1024];
    __shared__ int sab[1024];
    __shared__ int smask[64];
    __shared__ float sci[8];
    int tid = threadIdx.x;
    for (int i = tid; i < 1024; i += 256) {
        int pair = i >> 6, c = i & 63;
        float bvv = -FLT_MAX;
        int bbb = 1 << 30;
        for (int j = 0; j < 32; j++) {
            float v = g_pmax[(pair * 32 + j) * 64 + c];
            int b2 = g_pargb[(pair * 32 + j) * 64 + c];
            if (v > bvv || (v == bvv && b2 < bbb)) { bvv = v; bbb = b2; }
        }
        smax[i] = bvv;
        sab[i] = bbb;
    }
    if (tid < 64) {
        int off = (32 * tid + 2047) & 2047;
        smask[tid] = (obs[512 + off] == 1.0f) ? 1 : 0;
    }
    __syncthreads();
    if (tid == 0) {
        for (int i = 0; i < 16; i++) {
            float bestv = -FLT_MAX;
            int bestflat = -1;
            for (int c = 0; c < 64; c++) {
                if (smask[c]) continue;
                float v = smax[i * 64 + c];
                int flat = sab[i * 64 + c] * 64 + c;
                if (bestflat < 0 || v > bestv || (v == bestv && flat < bestflat)) {
                    bestv = v;
                    bestflat = flat;
                }
            }
            int ci = (bestflat < 0) ? 0 : bestflat;
            if (ci < 64) smask[ci] = 1;
            if (i >= 8) sci[i - 8] = (float)ci;
        }
    }
    __syncthreads();
    for (int i = tid; i < 32768; i += 256) out[i] = sci[i >> 12];
}

extern "C" void kernel_launch(void* const* d_in, const int* in_sizes, int n_in,
                              void* d_out, int out_size) {
    const float* obs = (const float*)d_in[0];
    const float* Wenc = (const float*)d_in[1];
    const float* benc = (const float*)d_in[2];
    const float* Wk_nb = (const float*)d_in[3];
    const float* Wsel_nb = (const float*)d_in[4];
    const float* Wv_nb = (const float*)d_in[5];
    const float* bv_nb = (const float*)d_in[6];
    const float* Wk_poi = (const float*)d_in[7];
    const float* Wsel_poi = (const float*)d_in[8];
    float* out = (float*)d_out;

    k0_prep<<<192, 256>>>(Wsel_nb, Wk_nb, Wsel_poi, Wk_poi);
    k_ct<<<Bn, 256>>>(obs);
    k1_stage1<<<dim3(256, 8), 256>>>(obs, Wenc, benc);
    k2_mean1<<<16, 256>>>();
    k3_stage2<<<dim3(256, 8), 256>>>(obs, Wv_nb, bv_nb);
    k4_mean2<<<16, 256>>>();
    k5_stats<<<dim3(16, 32), 256>>>();
    k6_scan<<<1, 256>>>(obs, out);
}